// round 17
// baseline (speedup 1.0000x reference)
#include <cuda_runtime.h>
#include <cuda_fp16.h>
#include <mma.h>
#include <math.h>

using namespace nvcuda;

#define N_NODES 100000
#define NUM_GRAPHS 128
#define H1 4
#define C1 48
#define F1 192   // H1*C1
#define C2 96
#define D_IN 128
#define NEG_SLOPE 0.2f
#define E_MAX 1750000   // raw edges (1.6M) + self loops (100k) with slack

// ---------------- scratch (device globals; no allocation) ----------------
__device__ __half g_h1h[N_NODES * F1];      // fp16 gather table (layer 1)
__device__ __half g_h1rh[N_NODES * F1];     // layer1 output (relu'd, fp16 -> GEMM2 A)
__device__ __half g_h2h[N_NODES * C2];      // fp16 gather table (layer 2)
__device__ float g_asrc1[N_NODES * H1];
__device__ float g_adst1[N_NODES * H1];
__device__ float g_asrc2[N_NODES];
__device__ float g_adst2[N_NODES];
__device__ float g_pool[NUM_GRAPHS * C2];
__device__ float g_cnt[NUM_GRAPHS];
__device__ int g_src[E_MAX];
__device__ int g_dst[E_MAX];
__device__ int g_batch[N_NODES];
__device__ int g_is64;
__device__ int g_deg[N_NODES];
__device__ int g_off[N_NODES + 1];
__device__ int g_cur[N_NODES];
__device__ int g_csr_src[E_MAX];

__device__ __forceinline__ float leaky(float s) {
    return s > 0.0f ? s : NEG_SLOPE * s;
}

// ---------------- init (zero counters only; stream B) ----------------
__global__ void init_kernel() {
    int i = blockIdx.x * blockDim.x + threadIdx.x;
    int stride = gridDim.x * blockDim.x;
    for (int k = i; k < N_NODES; k += stride) g_deg[k] = 0;
    for (int k = i; k < NUM_GRAPHS * C2; k += stride) g_pool[k] = 0.0f;
    for (int k = i; k < NUM_GRAPHS; k += stride) g_cnt[k] = 0.0f;
}

// ---------------- dtype sniff: int64 vs int32 index buffers ----------------
__global__ void sniff_kernel(const unsigned int* __restrict__ w) {
    __shared__ int any_nonzero;
    if (threadIdx.x == 0) any_nonzero = 0;
    __syncthreads();
    for (int i = threadIdx.x; i < 256; i += blockDim.x) {
        if (w[2 * i + 1] != 0u) any_nonzero = 1;
    }
    __syncthreads();
    if (threadIdx.x == 0) g_is64 = (any_nonzero == 0) ? 1 : 0;
}

__global__ void decode_edges(const void* __restrict__ ei_raw, int E0) {
    int e = blockIdx.x * blockDim.x + threadIdx.x;
    int Etot = E0 + N_NODES;
    if (e >= Etot) return;
    int src, dst;
    if (e < E0) {
        if (g_is64) {
            const long long* p = (const long long*)ei_raw;
            src = (int)p[e];
            dst = (int)p[E0 + e];
        } else {
            const int* p = (const int*)ei_raw;
            src = p[e];
            dst = p[E0 + e];
        }
    } else {
        src = dst = e - E0;
    }
    g_src[e] = src;
    g_dst[e] = dst;
    atomicAdd(&g_deg[dst], 1);
}

__global__ void decode_batch(const void* __restrict__ b_raw) {
    __shared__ int hist[NUM_GRAPHS];
    for (int i = threadIdx.x; i < NUM_GRAPHS; i += blockDim.x) hist[i] = 0;
    __syncthreads();
    int n = blockIdx.x * blockDim.x + threadIdx.x;
    if (n < N_NODES) {
        int b = g_is64 ? (int)((const long long*)b_raw)[n] : ((const int*)b_raw)[n];
        g_batch[n] = b;
        atomicAdd(&hist[b], 1);
    }
    __syncthreads();
    for (int i = threadIdx.x; i < NUM_GRAPHS; i += blockDim.x)
        if (hist[i]) atomicAdd(&g_cnt[i], (float)hist[i]);
}

__global__ void scan_kernel() {
    __shared__ int part[1024];
    int t = threadIdx.x;
    const int CH = (N_NODES + 1023) / 1024;
    int lo = t * CH, hi = min(lo + CH, N_NODES);
    int s = 0;
    for (int i = lo; i < hi; i++) s += g_deg[i];
    part[t] = s;
    __syncthreads();
    for (int o = 1; o < 1024; o <<= 1) {
        int v = (t >= o) ? part[t - o] : 0;
        __syncthreads();
        part[t] += v;
        __syncthreads();
    }
    int base = (t > 0) ? part[t - 1] : 0;
    for (int i = lo; i < hi; i++) {
        g_off[i] = base;
        g_cur[i] = base;
        base += g_deg[i];
    }
    if (t == 1023) g_off[N_NODES] = part[1023];
}

__global__ void scatter_kernel(int Etot) {
    int e = blockIdx.x * blockDim.x + threadIdx.x;
    if (e >= Etot) return;
    int pos = atomicAdd(&g_cur[g_dst[e]], 1);
    g_csr_src[pos] = g_src[e];
}

// ---------------- GEMM1 (HMMA): [M,128](fp32->fp16)@[128,192](fp16) ---------
// Block: 128 rows x full N=192. 8 warps; warp w owns rows [w*16, w*16+16),
// 12 m16n16k16 fragments across N. Full-N => complete attn1 sums, direct store.
// Head boundaries: head = f/3 (48 = 3 fragments).
__global__ void __launch_bounds__(256) hgemm1_kernel(const float* __restrict__ A,
                                                     const float* __restrict__ B,
                                                     __half* __restrict__ Ch,
                                                     const float* __restrict__ a_src,
                                                     const float* __restrict__ a_dst,
                                                     int M) {
    __shared__ __half Bsm[16 * F1];      // 6 KB (W1 K-chunk, fp16)
    __shared__ __half Asm[128 * 16];     // 4 KB
    __shared__ float stage[8 * 320];     // 10 KB epilogue

    int tid = threadIdx.x;
    int w = tid >> 5;
    int lane = tid & 31;
    int row0 = blockIdx.x * 128;

    wmma::fragment<wmma::accumulator, 16, 16, 16, float> acc[12];
#pragma unroll
    for (int f = 0; f < 12; f++) wmma::fill_fragment(acc[f], 0.0f);

    for (int k0 = 0; k0 < D_IN; k0 += 16) {
        // stage B chunk 16x192 (fp32 -> fp16, pairwise)
        for (int i = tid; i < 16 * F1 / 2; i += 256) {
            float2 v = *(const float2*)&B[(size_t)k0 * F1 + 2 * i];
            ((__half2*)Bsm)[i] = __floats2half2_rn(v.x, v.y);
        }
        // stage A chunk 128x16 (fp32 -> fp16)
        {
            int r = tid >> 1;
            int h8 = (tid & 1) * 8;
            int gr = row0 + r;
            __align__(16) __half hb[8];
            if (gr < M) {
                float4 v0 = *(const float4*)&A[(size_t)gr * D_IN + k0 + h8];
                float4 v1 = *(const float4*)&A[(size_t)gr * D_IN + k0 + h8 + 4];
                hb[0] = __float2half(v0.x); hb[1] = __float2half(v0.y);
                hb[2] = __float2half(v0.z); hb[3] = __float2half(v0.w);
                hb[4] = __float2half(v1.x); hb[5] = __float2half(v1.y);
                hb[6] = __float2half(v1.z); hb[7] = __float2half(v1.w);
            } else {
#pragma unroll
                for (int c = 0; c < 8; c++) hb[c] = __float2half(0.0f);
            }
            *(uint4*)&Asm[r * 16 + h8] = *(uint4*)hb;
        }
        __syncthreads();

        wmma::fragment<wmma::matrix_a, 16, 16, 16, __half, wmma::row_major> af;
        wmma::load_matrix_sync(af, &Asm[(w * 16) * 16], 16);
#pragma unroll
        for (int f = 0; f < 12; f++) {
            wmma::fragment<wmma::matrix_b, 16, 16, 16, __half, wmma::row_major> bf;
            wmma::load_matrix_sync(bf, &Bsm[f * 16], F1);
            wmma::mma_sync(acc[f], af, bf, acc[f]);
        }
        __syncthreads();
    }

    // epilogue: per-warp stage, per-row per-head attn dots + fp16 table stores
    float* ws = stage + w * 320;
    int erow = lane & 15;
    int ehalf = lane >> 4;
    int gr = row0 + w * 16 + erow;
    float psh[4] = {0.f, 0.f, 0.f, 0.f};
    float pdh[4] = {0.f, 0.f, 0.f, 0.f};

#pragma unroll
    for (int f = 0; f < 12; f++) {
        wmma::store_matrix_sync(ws, acc[f], 20, wmma::mem_row_major);
        __syncwarp();
        int c0 = f * 16 + ehalf * 8;
        int h = f / 3;
        const float* rowp = ws + erow * 20 + ehalf * 8;
        __align__(16) __half hbuf[8];
        float ps = 0.f, pd = 0.f;
#pragma unroll
        for (int c = 0; c < 8; c++) {
            float v = rowp[c];
            ps += v * a_src[c0 + c];
            pd += v * a_dst[c0 + c];
            hbuf[c] = __float2half(v);
        }
        psh[h] += ps;
        pdh[h] += pd;
        if (gr < M) *(uint4*)&Ch[(size_t)gr * F1 + c0] = *(uint4*)hbuf;
        __syncwarp();
    }

#pragma unroll
    for (int h = 0; h < 4; h++) {
        psh[h] += __shfl_down_sync(0xffffffffu, psh[h], 16);
        pdh[h] += __shfl_down_sync(0xffffffffu, pdh[h], 16);
    }
    if (lane < 16 && gr < M) {
        *(float4*)&g_asrc1[gr * H1] = make_float4(psh[0], psh[1], psh[2], psh[3]);
        *(float4*)&g_adst1[gr * H1] = make_float4(pdh[0], pdh[1], pdh[2], pdh[3]);
    }
}

// ---------------- GEMM2 (HMMA): [M,192](fp16)@[192,96](fp16) + fused attn2 --
__global__ void __launch_bounds__(256) hgemm2_kernel(const __half* __restrict__ A,
                                                     const float* __restrict__ B,
                                                     __half* __restrict__ Ch,
                                                     const float* __restrict__ a_src,
                                                     const float* __restrict__ a_dst,
                                                     int M) {
    __shared__ __half Bsm[F1 * C2];      // 36864 B; reused as epilogue stage
    __shared__ __half Asm[128 * 16];     // 4096 B

    int tid = threadIdx.x;
    int w = tid >> 5;
    int lane = tid & 31;
    int row0 = blockIdx.x * 128;

    // stage B once (fp32 -> fp16)
    for (int i = tid; i < F1 * C2; i += 256) Bsm[i] = __float2half(B[i]);
    __syncthreads();

    wmma::fragment<wmma::accumulator, 16, 16, 16, float> acc[6];
#pragma unroll
    for (int f = 0; f < 6; f++) wmma::fill_fragment(acc[f], 0.0f);

    for (int k0 = 0; k0 < F1; k0 += 16) {
        {
            int r = tid >> 1;
            int h8 = (tid & 1) * 8;
            int gr = row0 + r;
            uint4 v = make_uint4(0u, 0u, 0u, 0u);
            if (gr < M) v = *(const uint4*)&A[(size_t)gr * F1 + k0 + h8];
            *(uint4*)&Asm[r * 16 + h8] = v;
        }
        __syncthreads();
        wmma::fragment<wmma::matrix_a, 16, 16, 16, __half, wmma::row_major> af;
        wmma::load_matrix_sync(af, &Asm[(w * 16) * 16], 16);
#pragma unroll
        for (int f = 0; f < 6; f++) {
            wmma::fragment<wmma::matrix_b, 16, 16, 16, __half, wmma::row_major> bf;
            wmma::load_matrix_sync(bf, &Bsm[k0 * C2 + f * 16], C2);
            wmma::mma_sync(acc[f], af, bf, acc[f]);
        }
        __syncthreads();
    }

    // epilogue: full-N block => complete attn2 sums, direct store
    float* stage = (float*)Bsm;
    float* ws = stage + w * 320;
    int erow = lane & 15;
    int ehalf = lane >> 4;
    int gr = row0 + w * 16 + erow;
    float ps = 0.f, pd = 0.f;

#pragma unroll
    for (int f = 0; f < 6; f++) {
        wmma::store_matrix_sync(ws, acc[f], 20, wmma::mem_row_major);
        __syncwarp();
        int c0 = f * 16 + ehalf * 8;
        const float* rowp = ws + erow * 20 + ehalf * 8;
        __align__(16) __half hbuf[8];
#pragma unroll
        for (int c = 0; c < 8; c++) {
            float v = rowp[c];
            ps += v * a_src[c0 + c];
            pd += v * a_dst[c0 + c];
            hbuf[c] = __float2half(v);
        }
        if (gr < M) *(uint4*)&Ch[(size_t)gr * C2 + c0] = *(uint4*)hbuf;
        __syncwarp();
    }

    ps += __shfl_down_sync(0xffffffffu, ps, 16);
    pd += __shfl_down_sync(0xffffffffu, pd, 16);
    if (lane < 16 && gr < M) {
        g_asrc2[gr] = ps;
        g_adst2[gr] = pd;
    }
}

// ---------------- layer 1 fused: late-divide softmax, smem transpose --------
__global__ void gat1_kernel(const float* __restrict__ b1) {
    __shared__ float4 sp[8][32];
    __shared__ int ssrc[8][32];
    int node = (blockIdx.x * blockDim.x + threadIdx.x) >> 5;
    int w = (threadIdx.x >> 5) & 7;
    int lane = threadIdx.x & 31;
    if (node >= N_NODES) return;
    int start = g_off[node], end = g_off[node + 1];

    float4 ad = *(const float4*)&g_adst1[node * H1];

    float4 den = make_float4(0.f, 0.f, 0.f, 0.f);
    float acc[6] = {0.f, 0.f, 0.f, 0.f, 0.f, 0.f};

    for (int base = start; base < end; base += 32) {
        int idx = base + lane;
        float4 p = make_float4(0.f, 0.f, 0.f, 0.f);
        int s = 0;
        if (idx < end) {
            s = g_csr_src[idx];
            float4 as = *(const float4*)&g_asrc1[s * H1];
            p.x = __expf(leaky(as.x + ad.x));
            p.y = __expf(leaky(as.y + ad.y));
            p.z = __expf(leaky(as.z + ad.z));
            p.w = __expf(leaky(as.w + ad.w));
            den.x += p.x; den.y += p.y; den.z += p.z; den.w += p.w;
        }
        __syncwarp();
        sp[w][lane] = p;
        ssrc[w][lane] = s;
        __syncwarp();

        int cnt = min(32, end - base);
        for (int j = 0; j < cnt; j++) {
            float4 p4 = sp[w][j];
            int src = ssrc[w][j];
            const __half* hp = &g_h1h[(size_t)src * F1];
#pragma unroll
            for (int k = 0; k < 6; k++) {
                int c = k * 32 + lane;
                float pe = (c < 48) ? p4.x : (c < 96) ? p4.y : (c < 144) ? p4.z : p4.w;
                acc[k] += __half2float(hp[c]) * pe;
            }
        }
    }

#pragma unroll
    for (int o = 16; o > 0; o >>= 1) {
        den.x += __shfl_xor_sync(0xffffffffu, den.x, o);
        den.y += __shfl_xor_sync(0xffffffffu, den.y, o);
        den.z += __shfl_xor_sync(0xffffffffu, den.z, o);
        den.w += __shfl_xor_sync(0xffffffffu, den.w, o);
    }
    float inv0 = 1.0f / den.x, inv1 = 1.0f / den.y, inv2 = 1.0f / den.z, inv3 = 1.0f / den.w;

#pragma unroll
    for (int k = 0; k < 6; k++) {
        int c = k * 32 + lane;
        float inv = (c < 48) ? inv0 : (c < 96) ? inv1 : (c < 144) ? inv2 : inv3;
        g_h1rh[(size_t)node * F1 + c] = __float2half(fmaxf(acc[k] * inv + b1[c], 0.0f));
    }
}

// ---------------- layer 2 fused: late-divide softmax + pool -----------------
__global__ void gat2_kernel(const float* __restrict__ b2) {
    __shared__ float sp[8][32];
    __shared__ int ssrc[8][32];
    int node = (blockIdx.x * blockDim.x + threadIdx.x) >> 5;
    int w = (threadIdx.x >> 5) & 7;
    int lane = threadIdx.x & 31;
    if (node >= N_NODES) return;
    int start = g_off[node], end = g_off[node + 1];

    float ad = g_adst2[node];
    float den = 0.0f;
    float acc[3] = {0.f, 0.f, 0.f};

    for (int base = start; base < end; base += 32) {
        int idx = base + lane;
        float p = 0.0f;
        int s = 0;
        if (idx < end) {
            s = g_csr_src[idx];
            p = __expf(leaky(g_asrc2[s] + ad));
            den += p;
        }
        __syncwarp();
        sp[w][lane] = p;
        ssrc[w][lane] = s;
        __syncwarp();

        int cnt = min(32, end - base);
        for (int j = 0; j < cnt; j++) {
            float pe = sp[w][j];
            int src = ssrc[w][j];
            const __half* hp = &g_h2h[(size_t)src * C2];
#pragma unroll
            for (int k = 0; k < 3; k++) acc[k] += __half2float(hp[k * 32 + lane]) * pe;
        }
    }

#pragma unroll
    for (int o = 16; o > 0; o >>= 1) den += __shfl_xor_sync(0xffffffffu, den, o);
    float inv = 1.0f / den;

    int gp = g_batch[node] * C2;
#pragma unroll
    for (int k = 0; k < 3; k++) {
        int c = k * 32 + lane;
        float v = fmaxf(acc[k] * inv + b2[c], 0.0f);
        atomicAdd(&g_pool[gp + c], v);
    }
}

// ---------------- final MLP: one block per graph ----------------
__global__ void mlp_kernel(const float* __restrict__ fc1_w, const float* __restrict__ fc1_b,
                           const float* __restrict__ fc2_w, const float* __restrict__ fc2_b,
                           float* __restrict__ out) {
    __shared__ float p[C2];
    __shared__ float z[192];
    int g = blockIdx.x;
    int t = threadIdx.x;
    float inv = 1.0f / fmaxf(g_cnt[g], 1.0f);
    if (t < C2) p[t] = g_pool[g * C2 + t] * inv;
    __syncthreads();
    float acc = fc1_b[t];
#pragma unroll
    for (int k = 0; k < C2; k++) acc += p[k] * fc1_w[k * 192 + t];
    z[t] = fmaxf(acc, 0.0f);
    __syncthreads();
    if (t < C2) {
        float o = fc2_b[t];
#pragma unroll
        for (int k = 0; k < 192; k++) o += z[k] * fc2_w[k * C2 + t];
        out[g * C2 + t] = o;
    }
}

// ---------------- host launch (two-stream structure) ------------------------
extern "C" void kernel_launch(void* const* d_in, const int* in_sizes, int n_in,
                              void* d_out, int out_size) {
    const float* x = (const float*)d_in[0];
    const void* ei_raw = d_in[1];
    const void* batch_raw = d_in[2];
    const float* W1 = (const float*)d_in[3];
    const float* a_src1 = (const float*)d_in[4];
    const float* a_dst1 = (const float*)d_in[5];
    const float* b1 = (const float*)d_in[6];
    const float* W2 = (const float*)d_in[7];
    const float* a_src2 = (const float*)d_in[8];
    const float* a_dst2 = (const float*)d_in[9];
    const float* b2 = (const float*)d_in[10];
    const float* fc1_w = (const float*)d_in[11];
    const float* fc1_b = (const float*)d_in[12];
    const float* fc2_w = (const float*)d_in[13];
    const float* fc2_b = (const float*)d_in[14];
    float* out = (float*)d_out;

    int E0 = in_sizes[1] / 2;
    int Etot = E0 + N_NODES;

    __half *h1hp, *h1rhp, *h2hp;
    cudaGetSymbolAddress((void**)&h1hp, g_h1h);
    cudaGetSymbolAddress((void**)&h1rhp, g_h1rh);
    cudaGetSymbolAddress((void**)&h2hp, g_h2h);

    cudaStream_t sB;
    cudaStreamCreateWithFlags(&sB, cudaStreamNonBlocking);
    cudaEvent_t evFork, evJoin;
    cudaEventCreateWithFlags(&evFork, cudaEventDisableTiming);
    cudaEventCreateWithFlags(&evJoin, cudaEventDisableTiming);

    cudaEventRecord(evFork, 0);
    cudaStreamWaitEvent(sB, evFork, 0);

    // ---- stream B: CSR build + batch decode ----
    init_kernel<<<256, 256, 0, sB>>>();
    sniff_kernel<<<1, 256, 0, sB>>>((const unsigned int*)ei_raw);
    decode_edges<<<(Etot + 255) / 256, 256, 0, sB>>>(ei_raw, E0);
    decode_batch<<<(N_NODES + 255) / 256, 256, 0, sB>>>(batch_raw);
    scan_kernel<<<1, 1024, 0, sB>>>();
    scatter_kernel<<<(Etot + 255) / 256, 256, 0, sB>>>(Etot);
    cudaEventRecord(evJoin, sB);

    // ---- default: GEMM1 HMMA (+fused attn1, direct store) ----
    hgemm1_kernel<<<(N_NODES + 127) / 128, 256>>>(x, W1, h1hp, a_src1, a_dst1, N_NODES);
    cudaStreamWaitEvent(0, evJoin, 0);
    gat1_kernel<<<(N_NODES + 7) / 8, 256>>>(b1);

    // ---- default: GEMM2 HMMA (+fused attn2, direct store), gat2 ----
    hgemm2_kernel<<<(N_NODES + 127) / 128, 256>>>(h1rhp, W2, h2hp, a_src2, a_dst2, N_NODES);
    gat2_kernel<<<(N_NODES + 7) / 8, 256>>>(b2);

    // MLP head
    mlp_kernel<<<NUM_GRAPHS, 192>>>(fc1_w, fc1_b, fc2_w, fc2_b, out);
}